// round 7
// baseline (speedup 1.0000x reference)
#include <cuda_runtime.h>

#define N_COLS 65536
#define BATCH   256
#define ROWS_PER_BLOCK 8
#define THREADS 256
#define ROW_STRIDE (N_COLS / 2)   // row stride in float4 (x) / float2 (out) units

// Precomputed per-column coefficients {c0,c1,c2,c3} (1 MiB), indexed by column.
__device__ float4 g_wc[N_COLS];

// W16_TO_4 exactly as the reference builds it (W[3,1] written twice -> final 1).
__constant__ float c_W[4][16] = {
    { 0, 0, 0, 0,  0, 0, 0, 0,   1,  1,  1,  1,   1,  1,  1,  1},
    { 0, 0, 1, 1,  0, 0, 1, 1,  -1, -1,  0,  0,  -1, -1,  0,  0},
    { 0, 0, 0, 0,  1, 1, 1, 1,  -1, -1, -1, -1,   0,  0,  0,  0},
    { 0, 1,-1, 0, -1, 0,-2,-1,   1,  2,  0,  1,   0,  1, -1,  0}
};

// Kernel 1: per-column softmax over 16 logits + 4x16 projection.
// One column per thread: 65536 threads = 256 CTAs, coalesced 128B warp loads,
// exp computed exactly once per column chip-wide (MUFU floor ~2.5us).
__global__ void wc_precompute_kernel(const float* __restrict__ w) {
    int n = blockIdx.x * blockDim.x + threadIdx.x;

    float v[16];
    float m = -1e30f;
#pragma unroll
    for (int k = 0; k < 16; k++) {
        v[k] = __ldg(&w[k * N_COLS + n]);
        m = fmaxf(m, v[k]);
    }
    float s = 0.0f;
#pragma unroll
    for (int k = 0; k < 16; k++) {
        v[k] = __expf(v[k] - m);
        s += v[k];
    }
    float inv = 1.0f / s;

    float c0 = 0.f, c1 = 0.f, c2 = 0.f, c3 = 0.f;
#pragma unroll
    for (int k = 0; k < 16; k++) {
        c0 = fmaf(c_W[0][k], v[k], c0);
        c1 = fmaf(c_W[1][k], v[k], c1);
        c2 = fmaf(c_W[2][k], v[k], c2);
        c3 = fmaf(c_W[3][k], v[k], c3);
    }
    g_wc[n] = make_float4(c0 * inv, c1 * inv, c2 * inv, c3 * inv);
}

// Kernel 2: streaming bilinear gate (R4 structure + evict-first stores).
// Unit-stride LDG.128 across the warp, coeffs in registers across 8 rows,
// 8-deep load batches. Output stores use st.global.cs (evict-first): out is
// never re-read, so it should not displace x from L2 — x (~128MiB) nearly
// fits in L2 (~126MB) and stays hot across graph replays.
__global__ void __launch_bounds__(THREADS, 4)
gate_apply_kernel(const float4* __restrict__ x, float2* __restrict__ out) {
    const int t  = threadIdx.x;
    const int q0 = blockIdx.x * (2 * THREADS) + t;       // x-quad index
    const int q1 = q0 + THREADS;
    const int b0 = blockIdx.y * ROWS_PER_BLOCK;

    // Coefficients for 4 columns: 2*q0, 2*q0+1, 2*q1, 2*q1+1
    const float4 wA0 = g_wc[2 * q0];
    const float4 wA1 = g_wc[2 * q0 + 1];
    const float4 wB0 = g_wc[2 * q1];
    const float4 wB1 = g_wc[2 * q1 + 1];

    const float4* xq0 = x + (size_t)b0 * ROW_STRIDE + q0;
    const float4* xq1 = x + (size_t)b0 * ROW_STRIDE + q1;
    float2* oq0 = out + (size_t)b0 * ROW_STRIDE + q0;
    float2* oq1 = out + (size_t)b0 * ROW_STRIDE + q1;

#pragma unroll
    for (int h = 0; h < ROWS_PER_BLOCK / 4; h++) {
        float4 a[4], b[4];
#pragma unroll
        for (int i = 0; i < 4; i++) {
            a[i] = __ldg(xq0 + (size_t)i * ROW_STRIDE);
            b[i] = __ldg(xq1 + (size_t)i * ROW_STRIDE);
        }
#pragma unroll
        for (int i = 0; i < 4; i++) {
            float2 ra, rb;
            // out = c0 + c1*A + c2*B + c3*A*B = fma(A, fma(B,c3,c1), fma(B,c2,c0))
            ra.x = fmaf(a[i].x, fmaf(a[i].y, wA0.w, wA0.y), fmaf(a[i].y, wA0.z, wA0.x));
            ra.y = fmaf(a[i].z, fmaf(a[i].w, wA1.w, wA1.y), fmaf(a[i].w, wA1.z, wA1.x));
            rb.x = fmaf(b[i].x, fmaf(b[i].y, wB0.w, wB0.y), fmaf(b[i].y, wB0.z, wB0.x));
            rb.y = fmaf(b[i].z, fmaf(b[i].w, wB1.w, wB1.y), fmaf(b[i].w, wB1.z, wB1.x));
            __stcs(oq0 + (size_t)i * ROW_STRIDE, ra);   // evict-first store
            __stcs(oq1 + (size_t)i * ROW_STRIDE, rb);
        }
        xq0 += 4 * ROW_STRIDE;  xq1 += 4 * ROW_STRIDE;
        oq0 += 4 * ROW_STRIDE;  oq1 += 4 * ROW_STRIDE;
    }
}

extern "C" void kernel_launch(void* const* d_in, const int* in_sizes, int n_in,
                              void* d_out, int out_size) {
    const float* x = (const float*)d_in[0];   // (256, 131072)
    const float* w = (const float*)d_in[1];   // (16, 65536)
    float* out = (float*)d_out;               // (256, 65536)

    wc_precompute_kernel<<<N_COLS / 256, 256>>>(w);

    dim3 grid((N_COLS / 2) / (2 * THREADS), BATCH / ROWS_PER_BLOCK);  // (64, 32)
    gate_apply_kernel<<<grid, THREADS>>>((const float4*)x, (float2*)out);
}